// round 14
// baseline (speedup 1.0000x reference)
#include <cuda_runtime.h>
#include <math_constants.h>

#define Bn 4
#define Nn 4096
#define Pn 1024

#define KDE_B0 4
#define KDE_BLKS 256
#define CHUNK_B0 (KDE_B0 + KDE_BLKS)        // 260
#define NCHUNK 64                            // 64 chunks x 16 positions
#define CHUNK_BLKS (NCHUNK * Bn * 5)         // 1280
#define GRID_TOT (CHUNK_B0 + CHUNK_BLKS)     // 1540

__device__ int   g_fps[Bn * Pn];
__device__ float g_invden[Bn * Nn];
__device__ int   g_knn[Bn * Pn * 32];
__device__ int   g_kde_done[Bn];

__device__ __forceinline__ double ffma2(double a, double b, double c) {
    double d; asm("fma.rn.f32x2 %0, %1, %2, %3;" : "=d"(d) : "d"(a), "d"(b), "d"(c)); return d;
}
__device__ __forceinline__ double fadd2(double a, double b) {
    double d; asm("add.rn.f32x2 %0, %1, %2;" : "=d"(d) : "d"(a), "d"(b)); return d;
}
__device__ __forceinline__ double fmul2(double a, double b) {
    double d; asm("mul.rn.f32x2 %0, %1, %2;" : "=d"(d) : "d"(a), "d"(b)); return d;
}
__device__ __forceinline__ double dup2(float x) {
    double d; asm("mov.b64 %0, {%1, %1};" : "=d"(d) : "f"(x)); return d;
}
__device__ __forceinline__ double pack2(float lo, float hi) {
    double d; asm("mov.b64 %0, {%1, %2};" : "=d"(d) : "f"(lo), "f"(hi)); return d;
}
__device__ __forceinline__ float2 unpk(double a) {
    float2 r; asm("mov.b64 {%0, %1}, %2;" : "=f"(r.x), "=f"(r.y) : "d"(a)); return r;
}
__device__ __forceinline__ int ldcg(const int* p) {
    int v; asm volatile("ld.global.cg.s32 %0, [%1];" : "=r"(v) : "l"(p)); return v;
}
__device__ __forceinline__ void stcg(int* p, int v) {
    asm volatile("st.global.cg.s32 [%0], %1;" :: "l"(p), "r"(v));
}

__global__ void init_kernel() {
    int i = blockIdx.x * blockDim.x + threadIdx.x;
    if (i < Bn * Pn * 32) g_knn[i] = -1;
    if (i < Bn * Pn)      g_fps[i] = -1;
    if (i < Bn)           g_kde_done[i] = 0;
}

struct FK {
    float4 xyzn[Nn];
    float4 nxyz[Nn];
    unsigned long long st1[2][32];
};
#define REDP 129
struct MS {
    float W1s[128*128];
    float A1T[128*128];
    float W0s[19*128];
    float A0T[19*128];
    float red[32*REDP];
    float w2c0[128], hds[128], gdb[128], gmax[4], pts0[128];
    float wnl0[16], wnl1[16], wwn[96];
};

__global__ void __launch_bounds__(512, 1)
mega_kernel(const float* __restrict__ xyz, const float* __restrict__ feat,
            const float* __restrict__ w0, const float* __restrict__ w1,
            const float* __restrict__ w2, const float* __restrict__ wwn_g,
            const float* __restrict__ wnl0_g, const float* __restrict__ wnl1_g,
            const float* __restrict__ wnp, float* __restrict__ d_out)
{
    extern __shared__ unsigned char smraw[];
    int t = threadIdx.x;
    int bid = blockIdx.x;
    float* newxyz = d_out;
    float* outfeat = d_out + Bn * Pn * 3;

    if (bid < Bn) {
        // ================= FPS role =================
        FK& s = *reinterpret_cast<FK*>(smraw);
        int b = bid;
        const float* xb = xyz + b * Nn * 3;
        for (int i = t; i < Nn; i += 512) {
            float x = xb[i*3+0], y = xb[i*3+1], z = xb[i*3+2];
            s.xyzn[i] = make_float4(x, y, z, 0.f);
            s.nxyz[i] = make_float4(-x, -y, -z, 0.f);
        }
        if (t >= 16 && t < 32) {
            s.st1[0][t] = 0x00000000ffffffffull;
            s.st1[1][t] = 0x00000000ffffffffull;
        }
        __syncthreads();

        double px2[4], py2[4], pz2[4];
#pragma unroll
        for (int p = 0; p < 4; p++) {
            float4 a = s.xyzn[t + 1024*p];
            float4 c = s.xyzn[t + 1024*p + 512];
            px2[p] = pack2(a.x, c.x);
            py2[p] = pack2(a.y, c.y);
            pz2[p] = pack2(a.z, c.z);
        }
        float md[8];
#pragma unroll
        for (int j = 0; j < 8; j++) md[j] = CUDART_INF_F;

        if (t == 0) stcg(g_fps + b*Pn, 0);
        float4 nc = s.nxyz[0];
        double ncx = dup2(nc.x), ncy = dup2(nc.y), ncz = dup2(nc.z);
        int lane = t & 31, wid = t >> 5;

        for (int it = 1; it < Pn; ++it) {
#pragma unroll
            for (int p = 0; p < 4; p++) {
                double dx = fadd2(px2[p], ncx);
                double dy = fadd2(py2[p], ncy);
                double dz = fadd2(pz2[p], ncz);
                double d2 = ffma2(dz, dz, ffma2(dy, dy, fmul2(dx, dx)));
                float2 dd = unpk(d2);
                md[2*p]   = fminf(md[2*p],   dd.x);
                md[2*p+1] = fminf(md[2*p+1], dd.y);
            }
            float best = md[0];
#pragma unroll
            for (int j = 1; j < 8; j++) best = fmaxf(best, md[j]);
            int bi = t + 512*7;
#pragma unroll
            for (int j = 6; j >= 0; j--) bi = (md[j] == best) ? (t + 512*j) : bi;

            unsigned vb   = __float_as_uint(best);
            unsigned wmax = __reduce_max_sync(0xffffffffu, vb);
            unsigned cnd  = (vb == wmax) ? (unsigned)bi : 0xffffffffu;
            unsigned wmin = __reduce_min_sync(0xffffffffu, cnd);
            int buf = it & 1;
            if (lane == 0)
                s.st1[buf][wid] = ((unsigned long long)wmax << 32) | wmin;
            __syncthreads();
            unsigned long long e = s.st1[buf][lane];
            unsigned vb2 = (unsigned)(e >> 32), bi2 = (unsigned)e;
            unsigned m2  = __reduce_max_sync(0xffffffffu, vb2);
            unsigned c2  = (vb2 == m2) ? bi2 : 0xffffffffu;
            unsigned sel = __reduce_min_sync(0xffffffffu, c2);
            if (t == 0) stcg(g_fps + b*Pn + it, (int)sel);
            float4 nc2 = s.nxyz[sel];
            ncx = dup2(nc2.x); ncy = dup2(nc2.y); ncz = dup2(nc2.z);
        }
        __syncthreads();
        for (int o = t; o < Pn; o += 512) {
            int i = ldcg(g_fps + b*Pn + o);
            float4 v = s.xyzn[i];
            newxyz[(b*Pn + o)*3 + 0] = v.x;
            newxyz[(b*Pn + o)*3 + 1] = v.y;
            newxyz[(b*Pn + o)*3 + 2] = v.z;
        }
    } else if (bid < CHUNK_B0) {
        // ================= KDE role: 64 blocks/batch, 64 queries/block ======
        FK& s = *reinterpret_cast<FK*>(smraw);
        int kb = bid - KDE_B0;          // 0..255
        int b  = kb >> 6;               // 64 blocks per batch
        int qb = (kb & 63) * 64;        // 64 queries per block (4 per warp)
        const float* xb = xyz + b * Nn * 3;
        for (int i = t; i < Nn; i += 512) {
            float x = xb[i*3+0], y = xb[i*3+1], z = xb[i*3+2];
            s.xyzn[i] = make_float4(x, y, z, x*x + y*y + z*z);
        }
        __syncthreads();
        int w = t >> 5, lane = t & 31;
        const float R2 = 0.1f * 0.1f;
        float Rc  = sqrtf(0.05f);
        float cst = -3.0f * logf(Rc) - 1.5f * logf(2.0f * 3.1415926f);
        for (int qi = 0; qi < 4; qi++) {
            int q = qb + (w << 2) + qi;
            float4 qv = s.xyzn[q];
            float qx = qv.x, qy = qv.y, qz = qv.z, qn = qv.w;
            float ssum = 0.f; int cnt = 0;
            for (int j = lane; j < Nn; j += 32) {
                float4 pv = s.xyzn[j];
                float dot = qx*pv.x + qy*pv.y + qz*pv.z;
                float d2 = (qn + pv.w) - 2.0f * dot;
                if (d2 < R2) {
                    cnt++;
                    float gx = (pv.x-qx)/Rc, gy = (pv.y-qy)/Rc, gz = (pv.z-qz)/Rc;
                    ssum += expf(-0.5f*(gx*gx+gy*gy+gz*gz) + cst);
                }
            }
#pragma unroll
            for (int off = 16; off; off >>= 1) {
                ssum += __shfl_xor_sync(0xffffffffu, ssum, off);
                cnt  += __shfl_xor_sync(0xffffffffu, cnt,  off);
            }
            if (lane == 0) g_invden[b*Nn + q] = (float)cnt / ssum;
        }
        __syncthreads();
        if (t == 0) { __threadfence(); atomicAdd(&g_kde_done[b], 1); }
    } else {
        // ========== chunk-interleaved KNN + MAIN ==========
        int rel = bid - CHUNK_B0;        // 0..1279
        int c   = rel / 20;              // chunk of 16 positions
        int b   = (rel / 5) & 3;         // batch
        int sub = rel % 5;               // 0 = KNN, 1..4 = MAIN
        int pos0 = c * 16;

        if (sub == 0) {
            // ---- KNN: 16 warps, positions pos0..pos0+15 of batch b ----
            float4* pts = (float4*)smraw;
            const float* xb = xyz + b * Nn * 3;
            for (int i = t; i < Nn; i += 512) {
                float x = xb[i*3+0], y = xb[i*3+1], z = xb[i*3+2];
                pts[i] = make_float4(x, y, z, x*x + y*y + z*z);
            }
            __syncthreads();

            int w = t >> 5, lane = t & 31;
            int q = pos0 + w;
            const int* fp_p = g_fps + b*Pn + q;
            int fidx = ldcg(fp_p);
            while (fidx == -1) { __nanosleep(64); fidx = ldcg(fp_p); }
            float4 qv = pts[fidx];
            float qx = qv.x, qy = qv.y, qz = qv.z;
            float qn = qx*qx + qy*qy + qz*qz;

            float bd = CUDART_INF_F; int bix = 0;
            for (int base = 0; base < Nn; base += 32) {
                float4 pv = pts[base + lane];
                float dot = qx*pv.x + qy*pv.y + qz*pv.z;
                float d2 = (qn + pv.w) - 2.0f * dot;
                float worst = __shfl_sync(0xffffffffu, bd, 31);
                unsigned mask = __ballot_sync(0xffffffffu, d2 < worst);
                while (mask) {
                    int src = __ffs(mask) - 1; mask &= mask - 1;
                    float cd = __shfl_sync(0xffffffffu, d2, src);
                    float cw = __shfl_sync(0xffffffffu, bd, 31);
                    if (cd < cw) {
                        int pos = __popc(__ballot_sync(0xffffffffu, bd <= cd));
                        float up = __shfl_up_sync(0xffffffffu, bd, 1);
                        int  upi = __shfl_up_sync(0xffffffffu, bix, 1);
                        int  ci  = base + src;
                        if (lane >= pos) {
                            bd  = (lane == pos) ? cd : up;
                            bix = (lane == pos) ? ci : upi;
                        }
                    }
                }
            }
            stcg(g_knn + (b*Pn + q)*32 + lane, bix);
        } else {
            // ---- MAIN: groups b*1024 + pos0 + (sub-1)*4 .. +3 ----
            MS& s = *reinterpret_cast<MS*>(smraw);
            int tid = t;
            int gp0 = b*Pn + pos0 + (sub - 1)*4;
            int b0  = b;

            {
                const float4* src = (const float4*)w1;
                float4* dst = (float4*)s.W1s;
                for (int i = tid; i < 4096; i += 512) dst[i] = src[i];
            }
            for (int i = tid; i < 19*128; i += 512) s.W0s[i] = w0[i];
            if (tid < 128) s.w2c0[tid] = w2[tid * 256];
            if (tid < 16) { s.wnl0[tid] = wnl0_g[tid]; s.wnl1[tid] = wnl1_g[tid]; }
            if (tid >= 32 && tid < 128) s.wwn[tid - 32] = wwn_g[tid - 32];

            if (tid == 0) {
                while (ldcg(&g_kde_done[b0]) != 64) __nanosleep(128);
                __threadfence();
            }

            int my_idx = 0, my_r = 0;
            float cxv = 0.f, cyv = 0.f, czv = 0.f;
            if (tid < 128) {
                int r = tid, g = r >> 5, kk = r & 31;
                int gp = gp0 + g;
                const int* kp = g_knn + gp*32 + kk;
                int idx = ldcg(kp);
                while (idx == -1) { __nanosleep(64); idx = ldcg(kp); }
                my_idx = idx; my_r = r;
                const int* fpp = g_fps + b0*Pn + (gp & 1023);
                int fidx = ldcg(fpp);
                while (fidx == -1) { __nanosleep(64); fidx = ldcg(fpp); }
                const float* cp = xyz + (b0*Nn + fidx)*3;
                cxv = cp[0]; cyv = cp[1]; czv = cp[2];
            }
            __syncthreads();

            if (tid < 128) {
                int r = my_r, idx = my_idx;
                const float* xp = xyz + (b0*Nn + idx)*3;
                s.A0T[0*128 + r] = xp[0] - cxv;
                s.A0T[1*128 + r] = xp[1] - cyv;
                s.A0T[2*128 + r] = xp[2] - czv;
                const float4* fp = (const float4*)(feat + (b0*Nn + idx)*16);
#pragma unroll
                for (int c4 = 0; c4 < 4; c4++) {
                    float4 v = fp[c4];
                    s.A0T[(3+c4*4+0)*128 + r] = v.x;
                    s.A0T[(3+c4*4+1)*128 + r] = v.y;
                    s.A0T[(3+c4*4+2)*128 + r] = v.z;
                    s.A0T[(3+c4*4+3)*128 + r] = v.w;
                }
                s.gdb[r] = g_invden[b0*Nn + idx];
            }
            __syncthreads();

            if (tid < 4) {
                float m = -CUDART_INF_F;
                for (int kk = 0; kk < 32; kk++) m = fmaxf(m, s.gdb[tid*32 + kk]);
                s.gmax[tid] = m;
            }

            // GEMM1 transposed
            {
                int fg = tid >> 5, rg = tid & 31;
                int fb = fg * 8, rb = rg * 4;
                float acc[8][4];
#pragma unroll
                for (int i = 0; i < 8; i++)
#pragma unroll
                    for (int j = 0; j < 4; j++) acc[i][j] = 0.f;
                for (int ch = 0; ch < 19; ch++) {
                    float4 wA = *(const float4*)&s.W0s[ch*128 + fb];
                    float4 wB = *(const float4*)&s.W0s[ch*128 + fb + 4];
                    float4 aA = *(const float4*)&s.A0T[ch*128 + rb];
                    float wv[8] = {wA.x,wA.y,wA.z,wA.w,wB.x,wB.y,wB.z,wB.w};
                    float av[4] = {aA.x,aA.y,aA.z,aA.w};
#pragma unroll
                    for (int i = 0; i < 8; i++)
#pragma unroll
                        for (int j = 0; j < 4; j++) acc[i][j] += wv[i]*av[j];
                }
#pragma unroll
                for (int i = 0; i < 8; i++) {
                    float4 v = make_float4(fmaxf(acc[i][0],0.f), fmaxf(acc[i][1],0.f),
                                           fmaxf(acc[i][2],0.f), fmaxf(acc[i][3],0.f));
                    *(float4*)&s.A1T[(fb+i)*128 + rb] = v;
                }
            }
            __syncthreads();

            // GEMM2 f32x2
            {
                int rg = tid >> 5, cg = tid & 31;
                int rb = rg * 8, cb = cg * 4;
                double acc2[4][4];
#pragma unroll
                for (int i = 0; i < 4; i++)
#pragma unroll
                    for (int j = 0; j < 4; j++) acc2[i][j] = 0.0;
                for (int k = 0; k < 128; k++) {
                    const double* ap = (const double*)&s.A1T[k*128 + rb];
                    double a0 = ap[0], a1 = ap[1], a2 = ap[2], a3 = ap[3];
                    float4 wv = *(const float4*)&s.W1s[k*128 + cb];
                    double w0d = dup2(wv.x), w1d = dup2(wv.y), w2d = dup2(wv.z), w3d = dup2(wv.w);
                    acc2[0][0] = ffma2(a0, w0d, acc2[0][0]);
                    acc2[0][1] = ffma2(a0, w1d, acc2[0][1]);
                    acc2[0][2] = ffma2(a0, w2d, acc2[0][2]);
                    acc2[0][3] = ffma2(a0, w3d, acc2[0][3]);
                    acc2[1][0] = ffma2(a1, w0d, acc2[1][0]);
                    acc2[1][1] = ffma2(a1, w1d, acc2[1][1]);
                    acc2[1][2] = ffma2(a1, w2d, acc2[1][2]);
                    acc2[1][3] = ffma2(a1, w3d, acc2[1][3]);
                    acc2[2][0] = ffma2(a2, w0d, acc2[2][0]);
                    acc2[2][1] = ffma2(a2, w1d, acc2[2][1]);
                    acc2[2][2] = ffma2(a2, w2d, acc2[2][2]);
                    acc2[2][3] = ffma2(a2, w3d, acc2[2][3]);
                    acc2[3][0] = ffma2(a3, w0d, acc2[3][0]);
                    acc2[3][1] = ffma2(a3, w1d, acc2[3][1]);
                    acc2[3][2] = ffma2(a3, w2d, acc2[3][2]);
                    acc2[3][3] = ffma2(a3, w3d, acc2[3][3]);
                }
                float p[8];
#pragma unroll
                for (int i = 0; i < 8; i++) p[i] = 0.f;
#pragma unroll
                for (int rp = 0; rp < 4; rp++)
#pragma unroll
                    for (int cc = 0; cc < 4; cc++) {
                        float2 v = unpk(acc2[rp][cc]);
                        float wc = s.w2c0[cb + cc];
                        p[2*rp]   += fmaxf(v.x, 0.f) * wc;
                        p[2*rp+1] += fmaxf(v.y, 0.f) * wc;
                    }
#pragma unroll
                for (int i = 0; i < 8; i++) s.red[cg*REDP + rb + i] = p[i];
            }
            __syncthreads();

            if (tid < 128) {
                int r = tid;
                float h = 0.f;
#pragma unroll
                for (int cc = 0; cc < 32; cc++) h += s.red[cc*REDP + r];
                h = fmaxf(h, 0.f);
                float scale = s.gdb[r] / s.gmax[r >> 5];
                float dsv = 0.f;
#pragma unroll
                for (int j = 0; j < 16; j++)
                    dsv += fmaxf(scale * s.wnl0[j], 0.f) * s.wnl1[j];
                dsv = fmaxf(dsv, 0.f);
                s.hds[r] = h * dsv;
            }
            __syncthreads();

            if (tid < 128) {
                int g = tid >> 5, wv = tid & 31;
                float w0v = s.wwn[wv], w1v = s.wwn[32+wv], w2v = s.wwn[64+wv];
                float acc = 0.f;
#pragma unroll
                for (int kk = 0; kk < 32; kk++) {
                    int r = g*32 + kk;
                    float gx = s.A0T[r], gy = s.A0T[128+r], gz = s.A0T[256+r];
                    float wt = fmaxf(gx*w0v + gy*w1v + gz*w2v, 0.f);
                    acc += s.hds[r] * wt;
                }
                s.pts0[g*32 + wv] = acc;
            }
            __syncthreads();

            {
                int f = tid & 255, half = tid >> 8;
                float acc0 = 0.f, acc1 = 0.f;
                for (int w = 0; w < 32; w++) {
                    float wv = wnp[w*256 + f];
                    acc0 += s.pts0[(2*half + 0)*32 + w] * wv;
                    acc1 += s.pts0[(2*half + 1)*32 + w] * wv;
                }
                outfeat[(gp0 + 2*half + 0)*256 + f] = fmaxf(acc0, 0.f);
                outfeat[(gp0 + 2*half + 1)*256 + f] = fmaxf(acc1, 0.f);
            }
        }
    }
}

extern "C" void kernel_launch(void* const* d_in, const int* in_sizes, int n_in,
                              void* d_out, int out_size)
{
    const float* xyz   = (const float*)d_in[0];
    const float* feat  = (const float*)d_in[1];
    const float* w0    = (const float*)d_in[2];
    const float* w1    = (const float*)d_in[3];
    const float* w2    = (const float*)d_in[4];
    const float* wwn   = (const float*)d_in[5];
    const float* wnl0  = (const float*)d_in[6];
    const float* wnl1  = (const float*)d_in[7];
    const float* wnp   = (const float*)d_in[8];

    int smem = (int)sizeof(MS);
    cudaFuncSetAttribute(mega_kernel, cudaFuncAttributeMaxDynamicSharedMemorySize, smem);

    init_kernel<<<(Bn*Pn*32 + 511)/512, 512>>>();
    mega_kernel<<<GRID_TOT, 512, smem>>>(xyz, feat, w0, w1, w2, wwn, wnl0, wnl1,
                                         wnp, (float*)d_out);
}

// round 17
// speedup vs baseline: 1.3789x; 1.3789x over previous
#include <cuda_runtime.h>
#include <math_constants.h>

#define Bn 4
#define Nn 4096
#define Pn 1024

#define KDE_B0 4
#define KDE_BLKS 256
#define KNN_B0 (KDE_B0 + KDE_BLKS)          // 260
#define KNN_BLKS 64
#define MAIN_B0 (KNN_B0 + KNN_BLKS)         // 324
#define MAIN_BLKS 1024
#define GRID_TOT (MAIN_B0 + MAIN_BLKS)      // 1348

__device__ int   g_fps[Bn * Pn];
__device__ float g_invden[Bn * Nn];
__device__ int   g_knn[Bn * Pn * 32];
__device__ int   g_kde_done[Bn];

__device__ __forceinline__ double ffma2(double a, double b, double c) {
    double d; asm("fma.rn.f32x2 %0, %1, %2, %3;" : "=d"(d) : "d"(a), "d"(b), "d"(c)); return d;
}
__device__ __forceinline__ double fadd2(double a, double b) {
    double d; asm("add.rn.f32x2 %0, %1, %2;" : "=d"(d) : "d"(a), "d"(b)); return d;
}
__device__ __forceinline__ double fmul2(double a, double b) {
    double d; asm("mul.rn.f32x2 %0, %1, %2;" : "=d"(d) : "d"(a), "d"(b)); return d;
}
__device__ __forceinline__ double dup2(float x) {
    double d; asm("mov.b64 %0, {%1, %1};" : "=d"(d) : "f"(x)); return d;
}
__device__ __forceinline__ double pack2(float lo, float hi) {
    double d; asm("mov.b64 %0, {%1, %2};" : "=d"(d) : "f"(lo), "f"(hi)); return d;
}
__device__ __forceinline__ float2 unpk(double a) {
    float2 r; asm("mov.b64 {%0, %1}, %2;" : "=f"(r.x), "=f"(r.y) : "d"(a)); return r;
}
__device__ __forceinline__ int ldcg(const int* p) {
    int v; asm volatile("ld.global.cg.s32 %0, [%1];" : "=r"(v) : "l"(p)); return v;
}
__device__ __forceinline__ void stcg(int* p, int v) {
    asm volatile("st.global.cg.s32 [%0], %1;" :: "l"(p), "r"(v));
}

__global__ void init_kernel() {
    int i = blockIdx.x * blockDim.x + threadIdx.x;
    if (i < Bn * Pn * 32) g_knn[i] = -1;
    if (i < Bn * Pn)      g_fps[i] = -1;
    if (i < Bn)           g_kde_done[i] = 0;
}

struct FK {
    float4 xyzn[Nn];
    float4 nxyz[Nn];
    unsigned long long st1[2][32];
};
#define REDP 129
struct MS {
    float W1s[128*128];
    float A1T[128*128];
    float W0s[19*128];
    float A0T[19*128];
    float red[32*REDP];
    float w2c0[128], hds[128], gdb[128], gmax[4], pts0[128];
    float wnl0[16], wnl1[16], wwn[96];
};

__global__ void __launch_bounds__(512, 1)
mega_kernel(const float* __restrict__ xyz, const float* __restrict__ feat,
            const float* __restrict__ w0, const float* __restrict__ w1,
            const float* __restrict__ w2, const float* __restrict__ wwn_g,
            const float* __restrict__ wnl0_g, const float* __restrict__ wnl1_g,
            const float* __restrict__ wnp, float* __restrict__ d_out)
{
    extern __shared__ unsigned char smraw[];
    int t = threadIdx.x;
    int bid = blockIdx.x;
    float* newxyz = d_out;
    float* outfeat = d_out + Bn * Pn * 3;

    if (bid < Bn) {
        // ================= FPS role =================
        FK& s = *reinterpret_cast<FK*>(smraw);
        int b = bid;
        const float* xb = xyz + b * Nn * 3;
        for (int i = t; i < Nn; i += 512) {
            float x = xb[i*3+0], y = xb[i*3+1], z = xb[i*3+2];
            s.xyzn[i] = make_float4(x, y, z, 0.f);
            s.nxyz[i] = make_float4(-x, -y, -z, 0.f);
        }
        if (t >= 16 && t < 32) {
            s.st1[0][t] = 0x00000000ffffffffull;
            s.st1[1][t] = 0x00000000ffffffffull;
        }
        __syncthreads();

        double px2[4], py2[4], pz2[4];
#pragma unroll
        for (int p = 0; p < 4; p++) {
            float4 a = s.xyzn[t + 1024*p];
            float4 c = s.xyzn[t + 1024*p + 512];
            px2[p] = pack2(a.x, c.x);
            py2[p] = pack2(a.y, c.y);
            pz2[p] = pack2(a.z, c.z);
        }
        float md[8];
#pragma unroll
        for (int j = 0; j < 8; j++) md[j] = CUDART_INF_F;

        if (t == 0) stcg(g_fps + b*Pn, 0);
        float4 nc = s.nxyz[0];
        double ncx = dup2(nc.x), ncy = dup2(nc.y), ncz = dup2(nc.z);
        int lane = t & 31, wid = t >> 5;

        for (int it = 1; it < Pn; ++it) {
#pragma unroll
            for (int p = 0; p < 4; p++) {
                double dx = fadd2(px2[p], ncx);
                double dy = fadd2(py2[p], ncy);
                double dz = fadd2(pz2[p], ncz);
                double d2 = ffma2(dz, dz, ffma2(dy, dy, fmul2(dx, dx)));
                float2 dd = unpk(d2);
                md[2*p]   = fminf(md[2*p],   dd.x);
                md[2*p+1] = fminf(md[2*p+1], dd.y);
            }
            float best = md[0];
#pragma unroll
            for (int j = 1; j < 8; j++) best = fmaxf(best, md[j]);
            int bi = t + 512*7;
#pragma unroll
            for (int j = 6; j >= 0; j--) bi = (md[j] == best) ? (t + 512*j) : bi;

            unsigned vb   = __float_as_uint(best);
            unsigned wmax = __reduce_max_sync(0xffffffffu, vb);
            unsigned cnd  = (vb == wmax) ? (unsigned)bi : 0xffffffffu;
            unsigned wmin = __reduce_min_sync(0xffffffffu, cnd);
            int buf = it & 1;
            if (lane == 0)
                s.st1[buf][wid] = ((unsigned long long)wmax << 32) | wmin;
            __syncthreads();
            unsigned long long e = s.st1[buf][lane];
            unsigned vb2 = (unsigned)(e >> 32), bi2 = (unsigned)e;
            unsigned m2  = __reduce_max_sync(0xffffffffu, vb2);
            unsigned c2  = (vb2 == m2) ? bi2 : 0xffffffffu;
            unsigned sel = __reduce_min_sync(0xffffffffu, c2);
            if (t == 0) stcg(g_fps + b*Pn + it, (int)sel);
            float4 nc2 = s.nxyz[sel];
            ncx = dup2(nc2.x); ncy = dup2(nc2.y); ncz = dup2(nc2.z);
        }
        __syncthreads();
        for (int o = t; o < Pn; o += 512) {
            int i = ldcg(g_fps + b*Pn + o);
            float4 v = s.xyzn[i];
            newxyz[(b*Pn + o)*3 + 0] = v.x;
            newxyz[(b*Pn + o)*3 + 1] = v.y;
            newxyz[(b*Pn + o)*3 + 2] = v.z;
        }
    } else if (bid < KNN_B0) {
        // ======== KDE: 64 blocks/batch, 64 queries/block (full coverage) ====
        FK& s = *reinterpret_cast<FK*>(smraw);
        int kb = bid - KDE_B0;          // 0..255
        int b  = kb >> 6;
        int qb = (kb & 63) * 64;
        const float* xb = xyz + b * Nn * 3;
        for (int i = t; i < Nn; i += 512) {
            float x = xb[i*3+0], y = xb[i*3+1], z = xb[i*3+2];
            s.xyzn[i] = make_float4(x, y, z, x*x + y*y + z*z);
        }
        __syncthreads();
        int w = t >> 5, lane = t & 31;
        const float R2 = 0.1f * 0.1f;
        float Rc  = sqrtf(0.05f);
        float cst = -3.0f * logf(Rc) - 1.5f * logf(2.0f * 3.1415926f);
        for (int qi = 0; qi < 4; qi++) {
            int q = qb + (w << 2) + qi;
            float4 qv = s.xyzn[q];
            float qx = qv.x, qy = qv.y, qz = qv.z, qn = qv.w;
            float ssum = 0.f; int cnt = 0;
            for (int j = lane; j < Nn; j += 32) {
                float4 pv = s.xyzn[j];
                float dot = qx*pv.x + qy*pv.y + qz*pv.z;
                float d2 = (qn + pv.w) - 2.0f * dot;
                if (d2 < R2) {
                    cnt++;
                    float gx = (pv.x-qx)/Rc, gy = (pv.y-qy)/Rc, gz = (pv.z-qz)/Rc;
                    ssum += expf(-0.5f*(gx*gx+gy*gy+gz*gz) + cst);
                }
            }
#pragma unroll
            for (int off = 16; off; off >>= 1) {
                ssum += __shfl_xor_sync(0xffffffffu, ssum, off);
                cnt  += __shfl_xor_sync(0xffffffffu, cnt,  off);
            }
            if (lane == 0) g_invden[b*Nn + q] = (float)cnt / ssum;
        }
        __syncthreads();
        if (t == 0) { __threadfence(); atomicAdd(&g_kde_done[b], 1); }
    } else if (bid < MAIN_B0) {
        // ===== KNN persistent: 16 blocks/batch, 4 position-chunks per warp ==
        float4* pts = (float4*)smraw;
        int kb = bid - KNN_B0;          // 0..63
        int b  = kb >> 4;
        int slot = kb & 15;
        const float* xb = xyz + b * Nn * 3;
        for (int i = t; i < Nn; i += 512) {
            float x = xb[i*3+0], y = xb[i*3+1], z = xb[i*3+2];
            pts[i] = make_float4(x, y, z, x*x + y*y + z*z);
        }
        __syncthreads();

        int w = t >> 5, lane = t & 31;
        for (int j = 0; j < 4; j++) {          // q in [0, 1024): 4*256 coverage
            int q = j*256 + slot*16 + w;
            const int* fp_p = g_fps + b*Pn + q;
            int fidx = ldcg(fp_p);
            while (fidx == -1) { __nanosleep(64); fidx = ldcg(fp_p); }
            float4 qv = pts[fidx];
            float qx = qv.x, qy = qv.y, qz = qv.z;
            float qn = qx*qx + qy*qy + qz*qz;

            float bd = CUDART_INF_F; int bix = 0;
            for (int base = 0; base < Nn; base += 32) {
                float4 pv = pts[base + lane];
                float dot = qx*pv.x + qy*pv.y + qz*pv.z;
                float d2 = (qn + pv.w) - 2.0f * dot;
                float worst = __shfl_sync(0xffffffffu, bd, 31);
                unsigned mask = __ballot_sync(0xffffffffu, d2 < worst);
                while (mask) {
                    int src = __ffs(mask) - 1; mask &= mask - 1;
                    float cd = __shfl_sync(0xffffffffu, d2, src);
                    float cw = __shfl_sync(0xffffffffu, bd, 31);
                    if (cd < cw) {
                        int pos = __popc(__ballot_sync(0xffffffffu, bd <= cd));
                        float up = __shfl_up_sync(0xffffffffu, bd, 1);
                        int  upi = __shfl_up_sync(0xffffffffu, bix, 1);
                        int  ci  = base + src;
                        if (lane >= pos) {
                            bd  = (lane == pos) ? cd : up;
                            bix = (lane == pos) ? ci : upi;
                        }
                    }
                }
            }
            stcg(g_knn + (b*Pn + q)*32 + lane, bix);
        }
    } else {
        // ===== MAIN: ordered by (position-block, batch) =====
        MS& s = *reinterpret_cast<MS*>(smraw);
        int tid = t;
        int rel = bid - MAIN_B0;        // 0..1023
        int posblk = rel >> 2;          // 0..255
        int b0  = rel & 3;
        int gp0 = b0*Pn + posblk*4;

        {
            const float4* src = (const float4*)w1;
            float4* dst = (float4*)s.W1s;
            for (int i = tid; i < 4096; i += 512) dst[i] = src[i];
        }
        for (int i = tid; i < 19*128; i += 512) s.W0s[i] = w0[i];
        if (tid < 128) s.w2c0[tid] = w2[tid * 256];
        if (tid < 16) { s.wnl0[tid] = wnl0_g[tid]; s.wnl1[tid] = wnl1_g[tid]; }
        if (tid >= 32 && tid < 128) s.wwn[tid - 32] = wwn_g[tid - 32];

        if (tid == 0) {
            while (ldcg(&g_kde_done[b0]) != 64) __nanosleep(128);
            __threadfence();
        }

        int my_idx = 0, my_r = 0;
        float cxv = 0.f, cyv = 0.f, czv = 0.f;
        if (tid < 128) {
            int r = tid, g = r >> 5, kk = r & 31;
            int gp = gp0 + g;
            const int* kp = g_knn + gp*32 + kk;
            int idx = ldcg(kp);
            while (idx == -1) { __nanosleep(64); idx = ldcg(kp); }
            my_idx = idx; my_r = r;
            const int* fpp = g_fps + b0*Pn + (gp & 1023);
            int fidx = ldcg(fpp);
            while (fidx == -1) { __nanosleep(64); fidx = ldcg(fpp); }
            const float* cp = xyz + (b0*Nn + fidx)*3;
            cxv = cp[0]; cyv = cp[1]; czv = cp[2];
        }
        __syncthreads();

        if (tid < 128) {
            int r = my_r, idx = my_idx;
            const float* xp = xyz + (b0*Nn + idx)*3;
            s.A0T[0*128 + r] = xp[0] - cxv;
            s.A0T[1*128 + r] = xp[1] - cyv;
            s.A0T[2*128 + r] = xp[2] - czv;
            const float4* fp = (const float4*)(feat + (b0*Nn + idx)*16);
#pragma unroll
            for (int c4 = 0; c4 < 4; c4++) {
                float4 v = fp[c4];
                s.A0T[(3+c4*4+0)*128 + r] = v.x;
                s.A0T[(3+c4*4+1)*128 + r] = v.y;
                s.A0T[(3+c4*4+2)*128 + r] = v.z;
                s.A0T[(3+c4*4+3)*128 + r] = v.w;
            }
            s.gdb[r] = g_invden[b0*Nn + idx];
        }
        __syncthreads();

        if (tid < 4) {
            float m = -CUDART_INF_F;
            for (int kk = 0; kk < 32; kk++) m = fmaxf(m, s.gdb[tid*32 + kk]);
            s.gmax[tid] = m;
        }

        // GEMM1 transposed
        {
            int fg = tid >> 5, rg = tid & 31;
            int fb = fg * 8, rb = rg * 4;
            float acc[8][4];
#pragma unroll
            for (int i = 0; i < 8; i++)
#pragma unroll
                for (int j = 0; j < 4; j++) acc[i][j] = 0.f;
            for (int ch = 0; ch < 19; ch++) {
                float4 wA = *(const float4*)&s.W0s[ch*128 + fb];
                float4 wB = *(const float4*)&s.W0s[ch*128 + fb + 4];
                float4 aA = *(const float4*)&s.A0T[ch*128 + rb];
                float wv[8] = {wA.x,wA.y,wA.z,wA.w,wB.x,wB.y,wB.z,wB.w};
                float av[4] = {aA.x,aA.y,aA.z,aA.w};
#pragma unroll
                for (int i = 0; i < 8; i++)
#pragma unroll
                    for (int j = 0; j < 4; j++) acc[i][j] += wv[i]*av[j];
            }
#pragma unroll
            for (int i = 0; i < 8; i++) {
                float4 v = make_float4(fmaxf(acc[i][0],0.f), fmaxf(acc[i][1],0.f),
                                       fmaxf(acc[i][2],0.f), fmaxf(acc[i][3],0.f));
                *(float4*)&s.A1T[(fb+i)*128 + rb] = v;
            }
        }
        __syncthreads();

        // GEMM2 f32x2
        {
            int rg = tid >> 5, cg = tid & 31;
            int rb = rg * 8, cb = cg * 4;
            double acc2[4][4];
#pragma unroll
            for (int i = 0; i < 4; i++)
#pragma unroll
                for (int j = 0; j < 4; j++) acc2[i][j] = 0.0;
            for (int k = 0; k < 128; k++) {
                const double* ap = (const double*)&s.A1T[k*128 + rb];
                double a0 = ap[0], a1 = ap[1], a2 = ap[2], a3 = ap[3];
                float4 wv = *(const float4*)&s.W1s[k*128 + cb];
                double w0d = dup2(wv.x), w1d = dup2(wv.y), w2d = dup2(wv.z), w3d = dup2(wv.w);
                acc2[0][0] = ffma2(a0, w0d, acc2[0][0]);
                acc2[0][1] = ffma2(a0, w1d, acc2[0][1]);
                acc2[0][2] = ffma2(a0, w2d, acc2[0][2]);
                acc2[0][3] = ffma2(a0, w3d, acc2[0][3]);
                acc2[1][0] = ffma2(a1, w0d, acc2[1][0]);
                acc2[1][1] = ffma2(a1, w1d, acc2[1][1]);
                acc2[1][2] = ffma2(a1, w2d, acc2[1][2]);
                acc2[1][3] = ffma2(a1, w3d, acc2[1][3]);
                acc2[2][0] = ffma2(a2, w0d, acc2[2][0]);
                acc2[2][1] = ffma2(a2, w1d, acc2[2][1]);
                acc2[2][2] = ffma2(a2, w2d, acc2[2][2]);
                acc2[2][3] = ffma2(a2, w3d, acc2[2][3]);
                acc2[3][0] = ffma2(a3, w0d, acc2[3][0]);
                acc2[3][1] = ffma2(a3, w1d, acc2[3][1]);
                acc2[3][2] = ffma2(a3, w2d, acc2[3][2]);
                acc2[3][3] = ffma2(a3, w3d, acc2[3][3]);
            }
            float p[8];
#pragma unroll
            for (int i = 0; i < 8; i++) p[i] = 0.f;
#pragma unroll
            for (int rp = 0; rp < 4; rp++)
#pragma unroll
                for (int cc = 0; cc < 4; cc++) {
                    float2 v = unpk(acc2[rp][cc]);
                    float wc = s.w2c0[cb + cc];
                    p[2*rp]   += fmaxf(v.x, 0.f) * wc;
                    p[2*rp+1] += fmaxf(v.y, 0.f) * wc;
                }
#pragma unroll
            for (int i = 0; i < 8; i++) s.red[cg*REDP + rb + i] = p[i];
        }
        __syncthreads();

        if (tid < 128) {
            int r = tid;
            float h = 0.f;
#pragma unroll
            for (int cc = 0; cc < 32; cc++) h += s.red[cc*REDP + r];
            h = fmaxf(h, 0.f);
            float scale = s.gdb[r] / s.gmax[r >> 5];
            float dsv = 0.f;
#pragma unroll
            for (int j = 0; j < 16; j++)
                dsv += fmaxf(scale * s.wnl0[j], 0.f) * s.wnl1[j];
            dsv = fmaxf(dsv, 0.f);
            s.hds[r] = h * dsv;
        }
        __syncthreads();

        if (tid < 128) {
            int g = tid >> 5, wv = tid & 31;
            float w0v = s.wwn[wv], w1v = s.wwn[32+wv], w2v = s.wwn[64+wv];
            float acc = 0.f;
#pragma unroll
            for (int kk = 0; kk < 32; kk++) {
                int r = g*32 + kk;
                float gx = s.A0T[r], gy = s.A0T[128+r], gz = s.A0T[256+r];
                float wt = fmaxf(gx*w0v + gy*w1v + gz*w2v, 0.f);
                acc += s.hds[r] * wt;
            }
            s.pts0[g*32 + wv] = acc;
        }
        __syncthreads();

        {
            int f = tid & 255, half = tid >> 8;
            float acc0 = 0.f, acc1 = 0.f;
            for (int w = 0; w < 32; w++) {
                float wv = wnp[w*256 + f];
                acc0 += s.pts0[(2*half + 0)*32 + w] * wv;
                acc1 += s.pts0[(2*half + 1)*32 + w] * wv;
            }
            outfeat[(gp0 + 2*half + 0)*256 + f] = fmaxf(acc0, 0.f);
            outfeat[(gp0 + 2*half + 1)*256 + f] = fmaxf(acc1, 0.f);
        }
    }
}

extern "C" void kernel_launch(void* const* d_in, const int* in_sizes, int n_in,
                              void* d_out, int out_size)
{
    const float* xyz   = (const float*)d_in[0];
    const float* feat  = (const float*)d_in[1];
    const float* w0    = (const float*)d_in[2];
    const float* w1    = (const float*)d_in[3];
    const float* w2    = (const float*)d_in[4];
    const float* wwn   = (const float*)d_in[5];
    const float* wnl0  = (const float*)d_in[6];
    const float* wnl1  = (const float*)d_in[7];
    const float* wnp   = (const float*)d_in[8];

    int smem = (int)sizeof(MS);
    cudaFuncSetAttribute(mega_kernel, cudaFuncAttributeMaxDynamicSharedMemorySize, smem);

    init_kernel<<<(Bn*Pn*32 + 511)/512, 512>>>();
    mega_kernel<<<GRID_TOT, 512, smem>>>(xyz, feat, w0, w1, w2, wwn, wnl0, wnl1,
                                         wnp, (float*)d_out);
}